// round 1
// baseline (speedup 1.0000x reference)
#include <cuda_runtime.h>
#include <cuda_bf16.h>
#include <math.h>

// Problem constants
#define BB 8
#define GG 16
#define NN_ 256
#define DD 768
#define EE 1536
#define SS 128
#define SEQ_ 512
#define TT (BB*GG*NN_)          // 32768 tokens
#define UVW (2*EE+SS)           // 3200

// ---------------- scratch (device globals; no allocations allowed) --------
__device__ float g_xn[(long long)TT*DD];            // 25.2M
__device__ float g_uv[(long long)TT*UVW];           // 104.9M
__device__ float g_qq[(long long)TT*SS];
__device__ float g_qkk[(long long)TT*SS];
__device__ float g_lq[(long long)TT*SS];
__device__ float g_lk[(long long)TT*SS];
__device__ float g_kv[(long long)BB*SS*EE];
__device__ float g_linv[(long long)TT*EE];
__device__ float g_linkv[(long long)BB*GG*SS*EE];
__device__ float g_linkv2[(long long)BB*GG*SS*EE];
__device__ float g_accb[(long long)TT*EE];
__device__ float g_qkm[(long long)BB*GG*NN_*NN_];
__device__ float g_gated[(long long)TT*EE];
__device__ float g_invf[64];
__device__ int   g_mn[BB*GG];
__device__ int   g_mx[BB*GG];

// ---------------- generic SGEMM: 128x128 tile, 8x8/thread, K-tile 8 -------
// C[m,n] = alpha * sum_k opA(m,k)*opB(k,n)  (+C if accumulate)
// epi: 0 none, 1 bias+silu, 2 bias+residual
template<int TA, int TB>
__global__ __launch_bounds__(256)
void sgemm_kernel(const float* __restrict__ A, const float* __restrict__ B,
                  float* __restrict__ C,
                  int M, int N, int K, int lda, int ldb, int ldc,
                  long long sA, long long sB, long long sC,
                  float alpha, int accumulate, int epi,
                  const float* __restrict__ bias,
                  const float* __restrict__ resid, int ldr)
{
    __shared__ float As[8][128];
    __shared__ float Bs[8][128];
    int z = blockIdx.z;
    A += (long long)z * sA; B += (long long)z * sB; C += (long long)z * sC;
    int tid = threadIdx.x;
    int bm = blockIdx.y * 128;
    int bn = blockIdx.x * 128;
    int r = tid >> 4, c = tid & 15;

    float acc[8][8];
#pragma unroll
    for (int i = 0; i < 8; i++)
#pragma unroll
        for (int j = 0; j < 8; j++) acc[i][j] = 0.f;

    for (int k0 = 0; k0 < K; k0 += 8) {
#pragma unroll
        for (int l = 0; l < 4; l++) {
            int e  = tid + l * 256;
            int kk = e >> 7;
            int m  = e & 127;
            int gk = k0 + kk;
            int gm = bm + m;
            float va = 0.f;
            if (gm < M && gk < K)
                va = TA ? A[(long long)gk * lda + gm] : A[(long long)gm * lda + gk];
            As[kk][m] = va;
            int gn = bn + m;
            float vb = 0.f;
            if (gn < N && gk < K)
                vb = TB ? B[(long long)gn * ldb + gk] : B[(long long)gk * ldb + gn];
            Bs[kk][m] = vb;
        }
        __syncthreads();
#pragma unroll
        for (int kk = 0; kk < 8; kk++) {
            float4 a0 = *(const float4*)&As[kk][r * 8];
            float4 a1 = *(const float4*)&As[kk][r * 8 + 4];
            float4 b0 = *(const float4*)&Bs[kk][c * 8];
            float4 b1 = *(const float4*)&Bs[kk][c * 8 + 4];
            float a[8] = {a0.x,a0.y,a0.z,a0.w,a1.x,a1.y,a1.z,a1.w};
            float b[8] = {b0.x,b0.y,b0.z,b0.w,b1.x,b1.y,b1.z,b1.w};
#pragma unroll
            for (int i = 0; i < 8; i++)
#pragma unroll
                for (int j = 0; j < 8; j++)
                    acc[i][j] = fmaf(a[i], b[j], acc[i][j]);
        }
        __syncthreads();
    }

#pragma unroll
    for (int i = 0; i < 8; i++) {
        int gm = bm + r * 8 + i;
        if (gm >= M) continue;
#pragma unroll
        for (int j = 0; j < 8; j++) {
            int gn = bn + c * 8 + j;
            if (gn >= N) continue;
            float v = acc[i][j] * alpha;
            long long off = (long long)gm * ldc + gn;
            if (accumulate) v += C[off];
            if (epi == 1) {
                v += bias[gn];
                v = v / (1.f + expf(-v));          // silu
            } else if (epi == 2) {
                v += bias[gn] + resid[(long long)gm * ldr + gn];
            }
            C[off] = v;
        }
    }
}

// ---------------- layernorm --------------------------------------------
__global__ void ln_kernel(const float* __restrict__ x, const float* __restrict__ w,
                          const float* __restrict__ b, float* __restrict__ y)
{
    int t = blockIdx.x;
    const float* row = x + (long long)t * DD;
    float* outp = y + (long long)t * DD;
    __shared__ float red[8];
    __shared__ float s_mu, s_rstd;
    int tid = threadIdx.x;          // 256
    float s = 0.f;
    for (int i = tid; i < DD; i += 256) s += row[i];
#pragma unroll
    for (int o = 16; o > 0; o >>= 1) s += __shfl_xor_sync(0xffffffffu, s, o);
    if ((tid & 31) == 0) red[tid >> 5] = s;
    __syncthreads();
    if (tid == 0) {
        float tot = 0.f;
        for (int i = 0; i < 8; i++) tot += red[i];
        s_mu = tot / (float)DD;
    }
    __syncthreads();
    float mu = s_mu;
    float vs = 0.f;
    for (int i = tid; i < DD; i += 256) { float d = row[i] - mu; vs += d * d; }
#pragma unroll
    for (int o = 16; o > 0; o >>= 1) vs += __shfl_xor_sync(0xffffffffu, vs, o);
    if ((tid & 31) == 0) red[tid >> 5] = vs;
    __syncthreads();
    if (tid == 0) {
        float tot = 0.f;
        for (int i = 0; i < 8; i++) tot += red[i];
        s_rstd = rsqrtf(tot / (float)DD + 1e-5f);
    }
    __syncthreads();
    float rstd = s_rstd;
    for (int i = tid; i < DD; i += 256)
        outp[i] = (row[i] - mu) * rstd * w[i] + b[i];
}

// ---------------- inv_freq (double precision, correctly rounded fp32) -----
__global__ void invf_kernel(float* g)
{
    int j = threadIdx.x;
    if (j < 64) g[j] = (float)exp(log(10000.0) * ((double)j / 64.0));
}

// ---------------- affine (gamma/beta) + RoPE → 4 components --------------
__global__ void rope_kernel(const float* __restrict__ uv, const float* __restrict__ gamma,
                            const float* __restrict__ beta, const float* __restrict__ invf,
                            float* __restrict__ qq, float* __restrict__ qk,
                            float* __restrict__ lq, float* __restrict__ lk)
{
    int t = blockIdx.x;             // token
    int j = threadIdx.x;            // 0..63
    int g = (t >> 8) & (GG - 1);
    int n = t & (NN_ - 1);
    float p = (float)((g << 8) + n);
    float arg = p * invf[j];
    float sn, cs;
    sincosf(arg, &sn, &cs);
    const float* zp = uv + (long long)t * UVW + 2 * EE;
    float z1 = zp[j], z2 = zp[j + 64];
    float* outs[4] = {qq, qk, lq, lk};
#pragma unroll
    for (int i = 0; i < 4; i++) {
        float a1 = z1 * gamma[i * SS + j]      + beta[i * SS + j];
        float a2 = z2 * gamma[i * SS + 64 + j] + beta[i * SS + 64 + j];
        float* o = outs[i] + (long long)t * SS;
        o[j]      = a1 * cs - a2 * sn;
        o[j + 64] = a2 * cs + a1 * sn;
    }
}

// ---------------- segment min/max per (b,g) -------------------------------
__global__ void minmax_kernel(const int* __restrict__ seg, int* __restrict__ mn,
                              int* __restrict__ mx)
{
    int bg = blockIdx.x;
    int tid = threadIdx.x;          // 256
    int v = seg[(long long)bg * NN_ + tid];
    int a = v, b = v;
#pragma unroll
    for (int o = 16; o > 0; o >>= 1) {
        a = min(a, __shfl_xor_sync(0xffffffffu, a, o));
        b = max(b, __shfl_xor_sync(0xffffffffu, b, o));
    }
    __shared__ int smn[8], smx[8];
    if ((tid & 31) == 0) { smn[tid >> 5] = a; smx[tid >> 5] = b; }
    __syncthreads();
    if (tid == 0) {
        int aa = smn[0], bb = smx[0];
        for (int i = 1; i < 8; i++) { aa = min(aa, smn[i]); bb = max(bb, smx[i]); }
        mn[bg] = aa; mx[bg] = bb;
    }
}

// ---------------- group mixing via segment-overlap mask -------------------
__global__ void mix_kernel(const float* __restrict__ lin_kv, const int* __restrict__ mn,
                           const int* __restrict__ mx, float* __restrict__ outp)
{
    const long long SE = (long long)SS * EE;   // 196608
    int bg = blockIdx.y;
    int b = bg >> 4, g = bg & 15;
    __shared__ float w[16];
    if (threadIdx.x < 16) {
        int h = threadIdx.x;
        int mng = mn[b * 16 + g], mxg = mx[b * 16 + g];
        int ov = (mng <= mx[b * 16 + h] && mxg >= mn[b * 16 + h]) ? 1 : 0;
        w[h] = (float)ov;
    }
    __syncthreads();
    if (threadIdx.x == 0) {
        float cnt = 0.f;
        for (int h = 0; h < 16; h++) cnt += w[h];
        float inv = 1.f / cnt;
        for (int h = 0; h < 16; h++) w[h] *= inv;
    }
    __syncthreads();
    long long idx = (long long)blockIdx.x * 256 + threadIdx.x;     // 0..SE
    const float* src = lin_kv + (long long)b * 16 * SE + idx;
    float acc = 0.f;
#pragma unroll
    for (int h = 0; h < 16; h++) acc += w[h] * src[(long long)h * SE];
    outp[(long long)bg * SE + idx] = acc;
}

// ---------------- relu(qk/n + toeplitz bias)^2 ---------------------------
__global__ void qkbias_kernel(float* __restrict__ qk, const float* __restrict__ w_rel)
{
    long long idx = (long long)blockIdx.x * 256 + threadIdx.x;
    int j = (int)(idx & 255);
    int i = (int)((idx >> 8) & 255);
    float v = qk[idx] * (1.0f / 256.0f) + w_rel[SEQ_ - 1 + j - i];
    v = fmaxf(v, 0.f);
    qk[idx] = v * v;
}

// ---------------- gate: u * (quadratic + linear) -------------------------
__global__ void gate_kernel(const float* __restrict__ uv, const float* __restrict__ acc,
                            float* __restrict__ outp)
{
    long long idx = (long long)blockIdx.x * 256 + threadIdx.x;   // over T*E
    long long t = idx / EE;
    int e = (int)(idx - t * EE);
    outp[idx] = uv[t * UVW + e] * acc[idx];
}

// ---------------- launch ---------------------------------------------------
extern "C" void kernel_launch(void* const* d_in, const int* in_sizes, int n_in,
                              void* d_out, int out_size)
{
    const float* inputs = (const float*)d_in[0];
    const int*   seg    = (const int*)  d_in[1];
    const float* ln_w   = (const float*)d_in[2];
    const float* ln_b   = (const float*)d_in[3];
    const float* W1     = (const float*)d_in[4];
    const float* b1     = (const float*)d_in[5];
    const float* gamma  = (const float*)d_in[6];
    const float* beta   = (const float*)d_in[7];
    const float* W2     = (const float*)d_in[8];
    const float* b2     = (const float*)d_in[9];
    const float* w_rel  = (const float*)d_in[10];
    float* outp = (float*)d_out;

    float *xn, *uv, *qq, *qkk, *lq, *lk, *kv, *linv, *linkv, *linkv2, *accb, *qkm, *gated, *invf;
    int *mn, *mx;
    cudaGetSymbolAddress((void**)&xn,    g_xn);
    cudaGetSymbolAddress((void**)&uv,    g_uv);
    cudaGetSymbolAddress((void**)&qq,    g_qq);
    cudaGetSymbolAddress((void**)&qkk,   g_qkk);
    cudaGetSymbolAddress((void**)&lq,    g_lq);
    cudaGetSymbolAddress((void**)&lk,    g_lk);
    cudaGetSymbolAddress((void**)&kv,    g_kv);
    cudaGetSymbolAddress((void**)&linv,  g_linv);
    cudaGetSymbolAddress((void**)&linkv, g_linkv);
    cudaGetSymbolAddress((void**)&linkv2,g_linkv2);
    cudaGetSymbolAddress((void**)&accb,  g_accb);
    cudaGetSymbolAddress((void**)&qkm,   g_qkm);
    cudaGetSymbolAddress((void**)&gated, g_gated);
    cudaGetSymbolAddress((void**)&invf,  g_invf);
    cudaGetSymbolAddress((void**)&mn,    g_mn);
    cudaGetSymbolAddress((void**)&mx,    g_mx);

    // 1. LayerNorm
    ln_kernel<<<TT, 256>>>(inputs, ln_w, ln_b, xn);

    // 2. uv = silu(xn @ W1 + b1)   [32768,768]x[768,3200]
    sgemm_kernel<0,0><<<dim3(25, 256, 1), 256>>>(
        xn, W1, uv, TT, UVW, DD, DD, UVW, UVW, 0, 0, 0,
        1.f, 0, 1, b1, nullptr, 0);

    // 3. inv_freq + RoPE components
    invf_kernel<<<1, 64>>>(invf);
    rope_kernel<<<TT, 64>>>(uv, gamma, beta, invf, qq, qkk, lq, lk);

    // 4. kv[b] = lin_k[b]^T @ v[b]   per b: [4096,128]^T x [4096,1536]
    sgemm_kernel<1,0><<<dim3(12, 1, BB), 256>>>(
        lk, uv + EE, kv, SS, EE, GG*NN_, SS, UVW, EE,
        (long long)GG*NN_*SS, (long long)GG*NN_*UVW, (long long)SS*EE,
        1.f, 0, 0, nullptr, nullptr, 0);

    // 5. lin_v[b] = lin_q[b] @ kv[b]   per b: [4096,128] x [128,1536]
    sgemm_kernel<0,0><<<dim3(12, 32, BB), 256>>>(
        lq, kv, linv, GG*NN_, EE, SS, SS, EE, EE,
        (long long)GG*NN_*SS, (long long)SS*EE, (long long)GG*NN_*EE,
        1.f, 0, 0, nullptr, nullptr, 0);

    // 6. lin_kv[bg] = lin_k[bg]^T @ lin_v[bg] / n   per bg: [256,128]^T x [256,1536]
    sgemm_kernel<1,0><<<dim3(12, 1, BB*GG), 256>>>(
        lk, linv, linkv, SS, EE, NN_, SS, EE, EE,
        (long long)NN_*SS, (long long)NN_*EE, (long long)SS*EE,
        1.f / (float)NN_, 0, 0, nullptr, nullptr, 0);

    // 7. segment mask mixing
    minmax_kernel<<<BB*GG, 256>>>(seg, mn, mx);
    mix_kernel<<<dim3((SS*EE)/256, BB*GG), 256>>>(linkv, mn, mx, linkv2);

    // 8. linear[bg] = lin_q[bg] @ lin_kv2[bg]   per bg: [256,128] x [128,1536]
    sgemm_kernel<0,0><<<dim3(12, 2, BB*GG), 256>>>(
        lq, linkv2, accb, NN_, EE, SS, SS, EE, EE,
        (long long)NN_*SS, (long long)SS*EE, (long long)NN_*EE,
        1.f, 0, 0, nullptr, nullptr, 0);

    // 9. qk[bg] = quad_q[bg] @ quad_k[bg]^T   per bg: [256,128] x [256,128]^T
    sgemm_kernel<0,1><<<dim3(2, 2, BB*GG), 256>>>(
        qq, qkk, qkm, NN_, NN_, SS, SS, SS, NN_,
        (long long)NN_*SS, (long long)NN_*SS, (long long)NN_*NN_,
        1.f, 0, 0, nullptr, nullptr, 0);

    // 10. kernel = relu(qk/n + bias)^2
    qkbias_kernel<<<(BB*GG*NN_*NN_)/256, 256>>>(qkm, w_rel);

    // 11. quadratic: accb += kernel[bg] @ v[bg]   per bg: [256,256] x [256,1536]
    sgemm_kernel<0,0><<<dim3(12, 2, BB*GG), 256>>>(
        qkm, uv + EE, accb, NN_, EE, NN_, NN_, UVW, EE,
        (long long)NN_*NN_, (long long)NN_*UVW, (long long)NN_*EE,
        1.f, 1, 0, nullptr, nullptr, 0);

    // 12. gated = u * (quadratic + linear)
    gate_kernel<<<((long long)TT*EE)/256, 256>>>(uv, accb, gated);

    // 13. out = gated @ W2 + b2 + shortcut   [32768,1536]x[1536,768]
    sgemm_kernel<0,0><<<dim3(6, 256, 1), 256>>>(
        gated, W2, outp, TT, DD, EE, EE, DD, DD, 0, 0, 0,
        1.f, 0, 2, b2, inputs, DD);
}

// round 2
// speedup vs baseline: 2.7343x; 2.7343x over previous
#include <cuda_runtime.h>
#include <cuda_bf16.h>
#include <math.h>
#include <stdint.h>

// Problem constants
#define BB 8
#define GG 16
#define NN_ 256
#define DD 768
#define EE 1536
#define SS 128
#define SEQ_ 512
#define TT (BB*GG*NN_)          // 32768 tokens
#define UVW (2*EE+SS)           // 3200

// ---------------- scratch (device globals; no allocations allowed) --------
__device__ float g_xn[(long long)TT*DD];
__device__ float g_uv[(long long)TT*UVW];
__device__ float g_qq[(long long)TT*SS];
__device__ float g_qkk[(long long)TT*SS];
__device__ float g_lq[(long long)TT*SS];
__device__ float g_lk[(long long)TT*SS];
__device__ float g_kv[(long long)BB*SS*EE];
__device__ float g_linv[(long long)TT*EE];
__device__ float g_linkv[(long long)BB*GG*SS*EE];
__device__ float g_linkv2[(long long)BB*GG*SS*EE];
__device__ float g_accb[(long long)TT*EE];
__device__ float g_qkm[(long long)BB*GG*NN_*NN_];
__device__ float g_gated[(long long)TT*EE];
__device__ float g_invf[64];
__device__ int   g_mn[BB*GG];
__device__ int   g_mx[BB*GG];

// ---------------- tf32 helpers -------------------------------------------
__device__ __forceinline__ uint32_t f2tf32(float f) {
    uint32_t u;
    asm("cvt.rna.tf32.f32 %0, %1;" : "=r"(u) : "f"(f));
    return u;
}

__device__ __forceinline__ void mma8(float& c0, float& c1, float& c2, float& c3,
                                     uint32_t a0, uint32_t a1, uint32_t a2, uint32_t a3,
                                     uint32_t b0, uint32_t b1)
{
    asm volatile(
        "mma.sync.aligned.m16n8k8.row.col.f32.tf32.tf32.f32 "
        "{%0,%1,%2,%3}, {%4,%5,%6,%7}, {%8,%9}, {%0,%1,%2,%3};"
        : "+f"(c0), "+f"(c1), "+f"(c2), "+f"(c3)
        : "r"(a0), "r"(a1), "r"(a2), "r"(a3), "r"(b0), "r"(b1));
}

// ---------------- tf32 tensor-core GEMM ----------------------------------
// 128x128 block tile, K-tile 16, 8 warps (2x4), warp tile 64x32.
// C[m,n] = alpha * sum_k opA(m,k)*opB(k,n)  (+C if accumulate)
// opA(m,k) = TA ? A[k*lda+m] : A[m*lda+k];  opB(k,n) = TB ? B[n*ldb+k] : B[k*ldb+n]
// epi: 0 none, 1 bias+silu, 2 bias+residual
// REQUIRES: M%128==0 (grid.y=M/128), N%128==0, K%16==0. All call sites satisfy this.
template<int TA, int TB>
__global__ __launch_bounds__(256, 2)
void tgemm_kernel(const float* __restrict__ A, const float* __restrict__ B,
                  float* __restrict__ C,
                  int M, int N, int K, int lda, int ldb, int ldc,
                  long long sA, long long sB, long long sC,
                  float alpha, int accumulate, int epi,
                  const float* __restrict__ bias,
                  const float* __restrict__ resid, int ldr)
{
    // stride-20 padded smem: conflict-free tf32 fragment loads
    __shared__ uint32_t As[128 * 20];
    __shared__ uint32_t Bs[128 * 20];

    int z = blockIdx.z;
    A += (long long)z * sA; B += (long long)z * sB; C += (long long)z * sC;
    int tid  = threadIdx.x;
    int lane = tid & 31;
    int warp = tid >> 5;
    int wm = (warp >> 2) * 64;       // warp M offset in tile
    int wn = (warp & 3) * 32;        // warp N offset in tile
    int bm = blockIdx.y * 128;
    int bn = blockIdx.x * 128;
    int g = lane >> 2, t = lane & 3;

    float acc[4][4][4];
#pragma unroll
    for (int mf = 0; mf < 4; mf++)
#pragma unroll
        for (int nf = 0; nf < 4; nf++)
#pragma unroll
            for (int i = 0; i < 4; i++) acc[mf][nf][i] = 0.f;

    for (int k0 = 0; k0 < K; k0 += 16) {
        // ---- global -> smem (with tf32 rounding) ----
#pragma unroll
        for (int l = 0; l < 8; l++) {
            int idx = l * 256 + tid;
            int m, k; float v;
            if (TA) { m = idx & 127; k = idx >> 7; v = A[(long long)(k0 + k) * lda + bm + m]; }
            else    { k = idx & 15;  m = idx >> 4; v = A[(long long)(bm + m) * lda + k0 + k]; }
            As[m * 20 + k] = f2tf32(v);
        }
#pragma unroll
        for (int l = 0; l < 8; l++) {
            int idx = l * 256 + tid;
            int n, k; float v;
            if (TB) { k = idx & 15;  n = idx >> 4; v = B[(long long)(bn + n) * ldb + k0 + k]; }
            else    { n = idx & 127; k = idx >> 7; v = B[(long long)(k0 + k) * ldb + bn + n]; }
            Bs[n * 20 + k] = f2tf32(v);
        }
        __syncthreads();

        // ---- two k=8 steps of mma ----
#pragma unroll
        for (int ks = 0; ks < 2; ks++) {
            int kk = ks * 8;
            uint32_t af[4][4], bf[4][2];
#pragma unroll
            for (int mf = 0; mf < 4; mf++) {
                int r = wm + mf * 16 + g;
                af[mf][0] = As[r * 20 + kk + t];
                af[mf][1] = As[(r + 8) * 20 + kk + t];
                af[mf][2] = As[r * 20 + kk + t + 4];
                af[mf][3] = As[(r + 8) * 20 + kk + t + 4];
            }
#pragma unroll
            for (int nf = 0; nf < 4; nf++) {
                int cn = wn + nf * 8 + g;
                bf[nf][0] = Bs[cn * 20 + kk + t];
                bf[nf][1] = Bs[cn * 20 + kk + t + 4];
            }
#pragma unroll
            for (int mf = 0; mf < 4; mf++)
#pragma unroll
                for (int nf = 0; nf < 4; nf++)
                    mma8(acc[mf][nf][0], acc[mf][nf][1], acc[mf][nf][2], acc[mf][nf][3],
                         af[mf][0], af[mf][1], af[mf][2], af[mf][3],
                         bf[nf][0], bf[nf][1]);
        }
        __syncthreads();
    }

    // ---- epilogue ----
#pragma unroll
    for (int mf = 0; mf < 4; mf++) {
#pragma unroll
        for (int nf = 0; nf < 4; nf++) {
#pragma unroll
            for (int i = 0; i < 4; i++) {
                int row = bm + wm + mf * 16 + g + ((i >= 2) ? 8 : 0);
                int col = bn + wn + nf * 8 + 2 * t + (i & 1);
                float v = acc[mf][nf][i] * alpha;
                long long off = (long long)row * ldc + col;
                if (accumulate) v += C[off];
                if (epi == 1) {
                    v += bias[col];
                    v = v / (1.f + expf(-v));          // silu
                } else if (epi == 2) {
                    v += bias[col] + resid[(long long)row * ldr + col];
                }
                C[off] = v;
            }
        }
    }
}

// ---------------- layernorm --------------------------------------------
__global__ void ln_kernel(const float* __restrict__ x, const float* __restrict__ w,
                          const float* __restrict__ b, float* __restrict__ y)
{
    int t = blockIdx.x;
    const float* row = x + (long long)t * DD;
    float* outp = y + (long long)t * DD;
    __shared__ float red[8];
    __shared__ float s_mu, s_rstd;
    int tid = threadIdx.x;          // 256
    float s = 0.f;
    for (int i = tid; i < DD; i += 256) s += row[i];
#pragma unroll
    for (int o = 16; o > 0; o >>= 1) s += __shfl_xor_sync(0xffffffffu, s, o);
    if ((tid & 31) == 0) red[tid >> 5] = s;
    __syncthreads();
    if (tid == 0) {
        float tot = 0.f;
        for (int i = 0; i < 8; i++) tot += red[i];
        s_mu = tot / (float)DD;
    }
    __syncthreads();
    float mu = s_mu;
    float vs = 0.f;
    for (int i = tid; i < DD; i += 256) { float d = row[i] - mu; vs += d * d; }
#pragma unroll
    for (int o = 16; o > 0; o >>= 1) vs += __shfl_xor_sync(0xffffffffu, vs, o);
    if ((tid & 31) == 0) red[tid >> 5] = vs;
    __syncthreads();
    if (tid == 0) {
        float tot = 0.f;
        for (int i = 0; i < 8; i++) tot += red[i];
        s_rstd = rsqrtf(tot / (float)DD + 1e-5f);
    }
    __syncthreads();
    float rstd = s_rstd;
    for (int i = tid; i < DD; i += 256)
        outp[i] = (row[i] - mu) * rstd * w[i] + b[i];
}

// ---------------- inv_freq (double precision, correctly rounded fp32) -----
__global__ void invf_kernel(float* g)
{
    int j = threadIdx.x;
    if (j < 64) g[j] = (float)exp(log(10000.0) * ((double)j / 64.0));
}

// ---------------- affine (gamma/beta) + RoPE -> 4 components --------------
__global__ void rope_kernel(const float* __restrict__ uv, const float* __restrict__ gamma,
                            const float* __restrict__ beta, const float* __restrict__ invf,
                            float* __restrict__ qq, float* __restrict__ qk,
                            float* __restrict__ lq, float* __restrict__ lk)
{
    int t = blockIdx.x;             // token
    int j = threadIdx.x;            // 0..63
    int g = (t >> 8) & (GG - 1);
    int n = t & (NN_ - 1);
    float p = (float)((g << 8) + n);
    float arg = p * invf[j];
    float sn, cs;
    sincosf(arg, &sn, &cs);
    const float* zp = uv + (long long)t * UVW + 2 * EE;
    float z1 = zp[j], z2 = zp[j + 64];
    float* outs[4] = {qq, qk, lq, lk};
#pragma unroll
    for (int i = 0; i < 4; i++) {
        float a1 = z1 * gamma[i * SS + j]      + beta[i * SS + j];
        float a2 = z2 * gamma[i * SS + 64 + j] + beta[i * SS + 64 + j];
        float* o = outs[i] + (long long)t * SS;
        o[j]      = a1 * cs - a2 * sn;
        o[j + 64] = a2 * cs + a1 * sn;
    }
}

// ---------------- segment min/max per (b,g) -------------------------------
__global__ void minmax_kernel(const int* __restrict__ seg, int* __restrict__ mn,
                              int* __restrict__ mx)
{
    int bg = blockIdx.x;
    int tid = threadIdx.x;          // 256
    int v = seg[(long long)bg * NN_ + tid];
    int a = v, b = v;
#pragma unroll
    for (int o = 16; o > 0; o >>= 1) {
        a = min(a, __shfl_xor_sync(0xffffffffu, a, o));
        b = max(b, __shfl_xor_sync(0xffffffffu, b, o));
    }
    __shared__ int smn[8], smx[8];
    if ((tid & 31) == 0) { smn[tid >> 5] = a; smx[tid >> 5] = b; }
    __syncthreads();
    if (tid == 0) {
        int aa = smn[0], bb = smx[0];
        for (int i = 1; i < 8; i++) { aa = min(aa, smn[i]); bb = max(bb, smx[i]); }
        mn[bg] = aa; mx[bg] = bb;
    }
}

// ---------------- group mixing via segment-overlap mask -------------------
__global__ void mix_kernel(const float* __restrict__ lin_kv, const int* __restrict__ mn,
                           const int* __restrict__ mx, float* __restrict__ outp)
{
    const long long SE = (long long)SS * EE;   // 196608
    int bg = blockIdx.y;
    int b = bg >> 4, g = bg & 15;
    __shared__ float w[16];
    if (threadIdx.x < 16) {
        int h = threadIdx.x;
        int mng = mn[b * 16 + g], mxg = mx[b * 16 + g];
        int ov = (mng <= mx[b * 16 + h] && mxg >= mn[b * 16 + h]) ? 1 : 0;
        w[h] = (float)ov;
    }
    __syncthreads();
    if (threadIdx.x == 0) {
        float cnt = 0.f;
        for (int h = 0; h < 16; h++) cnt += w[h];
        float inv = 1.f / cnt;
        for (int h = 0; h < 16; h++) w[h] *= inv;
    }
    __syncthreads();
    long long idx = (long long)blockIdx.x * 256 + threadIdx.x;     // 0..SE
    const float* src = lin_kv + (long long)b * 16 * SE + idx;
    float acc = 0.f;
#pragma unroll
    for (int h = 0; h < 16; h++) acc += w[h] * src[(long long)h * SE];
    outp[(long long)bg * SE + idx] = acc;
}

// ---------------- relu(qk/n + toeplitz bias)^2 ---------------------------
__global__ void qkbias_kernel(float* __restrict__ qk, const float* __restrict__ w_rel)
{
    long long idx = (long long)blockIdx.x * 256 + threadIdx.x;
    int j = (int)(idx & 255);
    int i = (int)((idx >> 8) & 255);
    float v = qk[idx] * (1.0f / 256.0f) + w_rel[SEQ_ - 1 + j - i];
    v = fmaxf(v, 0.f);
    qk[idx] = v * v;
}

// ---------------- gate: u * (quadratic + linear) -------------------------
__global__ void gate_kernel(const float* __restrict__ uv, const float* __restrict__ acc,
                            float* __restrict__ outp)
{
    long long idx = (long long)blockIdx.x * 256 + threadIdx.x;   // over T*E
    long long t = idx / EE;
    int e = (int)(idx - t * EE);
    outp[idx] = uv[t * UVW + e] * acc[idx];
}

// ---------------- launch ---------------------------------------------------
extern "C" void kernel_launch(void* const* d_in, const int* in_sizes, int n_in,
                              void* d_out, int out_size)
{
    const float* inputs = (const float*)d_in[0];
    const int*   seg    = (const int*)  d_in[1];
    const float* ln_w   = (const float*)d_in[2];
    const float* ln_b   = (const float*)d_in[3];
    const float* W1     = (const float*)d_in[4];
    const float* b1     = (const float*)d_in[5];
    const float* gamma  = (const float*)d_in[6];
    const float* beta   = (const float*)d_in[7];
    const float* W2     = (const float*)d_in[8];
    const float* b2     = (const float*)d_in[9];
    const float* w_rel  = (const float*)d_in[10];
    float* outp = (float*)d_out;

    float *xn, *uv, *qq, *qkk, *lq, *lk, *kv, *linv, *linkv, *linkv2, *accb, *qkm, *gated, *invf;
    int *mn, *mx;
    cudaGetSymbolAddress((void**)&xn,    g_xn);
    cudaGetSymbolAddress((void**)&uv,    g_uv);
    cudaGetSymbolAddress((void**)&qq,    g_qq);
    cudaGetSymbolAddress((void**)&qkk,   g_qkk);
    cudaGetSymbolAddress((void**)&lq,    g_lq);
    cudaGetSymbolAddress((void**)&lk,    g_lk);
    cudaGetSymbolAddress((void**)&kv,    g_kv);
    cudaGetSymbolAddress((void**)&linv,  g_linv);
    cudaGetSymbolAddress((void**)&linkv, g_linkv);
    cudaGetSymbolAddress((void**)&linkv2,g_linkv2);
    cudaGetSymbolAddress((void**)&accb,  g_accb);
    cudaGetSymbolAddress((void**)&qkm,   g_qkm);
    cudaGetSymbolAddress((void**)&gated, g_gated);
    cudaGetSymbolAddress((void**)&invf,  g_invf);
    cudaGetSymbolAddress((void**)&mn,    g_mn);
    cudaGetSymbolAddress((void**)&mx,    g_mx);

    // 1. LayerNorm
    ln_kernel<<<TT, 256>>>(inputs, ln_w, ln_b, xn);

    // 2. uv = silu(xn @ W1 + b1)   [32768,768]x[768,3200]
    tgemm_kernel<0,0><<<dim3(25, 256, 1), 256>>>(
        xn, W1, uv, TT, UVW, DD, DD, UVW, UVW, 0, 0, 0,
        1.f, 0, 1, b1, nullptr, 0);

    // 3. inv_freq + RoPE components
    invf_kernel<<<1, 64>>>(invf);
    rope_kernel<<<TT, 64>>>(uv, gamma, beta, invf, qq, qkk, lq, lk);

    // 4. kv[b] = lin_k[b]^T @ v[b]   per b: [4096,128]^T x [4096,1536]
    tgemm_kernel<1,0><<<dim3(12, 1, BB), 256>>>(
        lk, uv + EE, kv, SS, EE, GG*NN_, SS, UVW, EE,
        (long long)GG*NN_*SS, (long long)GG*NN_*UVW, (long long)SS*EE,
        1.f, 0, 0, nullptr, nullptr, 0);

    // 5. lin_v[b] = lin_q[b] @ kv[b]   per b: [4096,128] x [128,1536]
    tgemm_kernel<0,0><<<dim3(12, 32, BB), 256>>>(
        lq, kv, linv, GG*NN_, EE, SS, SS, EE, EE,
        (long long)GG*NN_*SS, (long long)SS*EE, (long long)GG*NN_*EE,
        1.f, 0, 0, nullptr, nullptr, 0);

    // 6. lin_kv[bg] = lin_k[bg]^T @ lin_v[bg] / n   per bg: [256,128]^T x [256,1536]
    tgemm_kernel<1,0><<<dim3(12, 1, BB*GG), 256>>>(
        lk, linv, linkv, SS, EE, NN_, SS, EE, EE,
        (long long)NN_*SS, (long long)NN_*EE, (long long)SS*EE,
        1.f / (float)NN_, 0, 0, nullptr, nullptr, 0);

    // 7. segment mask mixing
    minmax_kernel<<<BB*GG, 256>>>(seg, mn, mx);
    mix_kernel<<<dim3((SS*EE)/256, BB*GG), 256>>>(linkv, mn, mx, linkv2);

    // 8. linear[bg] = lin_q[bg] @ lin_kv2[bg]   per bg: [256,128] x [128,1536]
    tgemm_kernel<0,0><<<dim3(12, 2, BB*GG), 256>>>(
        lq, linkv2, accb, NN_, EE, SS, SS, EE, EE,
        (long long)NN_*SS, (long long)SS*EE, (long long)NN_*EE,
        1.f, 0, 0, nullptr, nullptr, 0);

    // 9. qk[bg] = quad_q[bg] @ quad_k[bg]^T   per bg: [256,128] x [256,128]^T
    tgemm_kernel<0,1><<<dim3(2, 2, BB*GG), 256>>>(
        qq, qkk, qkm, NN_, NN_, SS, SS, SS, NN_,
        (long long)NN_*SS, (long long)NN_*SS, (long long)NN_*NN_,
        1.f, 0, 0, nullptr, nullptr, 0);

    // 10. kernel = relu(qk/n + bias)^2
    qkbias_kernel<<<(BB*GG*NN_*NN_)/256, 256>>>(qkm, w_rel);

    // 11. quadratic: accb += kernel[bg] @ v[bg]   per bg: [256,256] x [256,1536]
    tgemm_kernel<0,0><<<dim3(12, 2, BB*GG), 256>>>(
        qkm, uv + EE, accb, NN_, EE, NN_, NN_, UVW, EE,
        (long long)NN_*NN_, (long long)NN_*UVW, (long long)NN_*EE,
        1.f, 1, 0, nullptr, nullptr, 0);

    // 12. gated = u * (quadratic + linear)
    gate_kernel<<<((long long)TT*EE)/256, 256>>>(uv, accb, gated);

    // 13. out = gated @ W2 + b2 + shortcut   [32768,1536]x[1536,768]
    tgemm_kernel<0,0><<<dim3(6, 256, 1), 256>>>(
        gated, W2, outp, TT, DD, EE, EE, DD, DD, 0, 0, 0,
        1.f, 0, 2, b2, inputs, DD);
}